// round 1
// baseline (speedup 1.0000x reference)
#include <cuda_runtime.h>
#include <math.h>

#define BB 16
#define C1 128
#define C2 256
#define KK 4
#define HH 80
#define WW 80
#define HW 6400
#define EPSF 1e-5f
#define NPXT 100   // 6400/64 px tiles in kernel A

// ---------------- scratch (static device globals; no allocs) ----------------
__device__ float g_y[BB * C2 * HW];            // post conv1+BN+SiLU feature (104.9 MB)
__device__ float g_partsum[BB * C2 * NPXT];    // per-(b,c) partial sums (deterministic)
__device__ float g_partsq [BB * C2 * NPXT];
__device__ float g_mu [BB * C2];
__device__ float g_inv[BB * C2];
__device__ float g_attn[BB * KK];
__device__ float g_aggw[BB * C2 * 9 * C2];     // [b][ic][tap][oc] (37.7 MB)
__device__ float g_aggb[BB * C2];

// ============================================================================
// Kernel A: y = SiLU(BN(x @ W1))  + per-(b,c) partial sum / sumsq over px tile
// grid (100, 4, 16), block 256.  Tile: 64 px x 64 oc, thread = 4oc x 4px.
// ============================================================================
__global__ void __launch_bounds__(256) k_conv1(
    const float* __restrict__ x, const float* __restrict__ w1,
    const float* __restrict__ bng, const float* __restrict__ bnb,
    const float* __restrict__ bnm, const float* __restrict__ bnv)
{
    __shared__ __align__(16) float xs[8][64];
    __shared__ __align__(16) float ws[8][64];
    __shared__ float red[64][17];

    const int b   = blockIdx.z;
    const int oc0 = blockIdx.y * 64;
    const int p0  = blockIdx.x * 64;
    const int tid = threadIdx.x;
    const int og  = tid >> 4;       // 0..15 (oc group of 4)
    const int pg  = tid & 15;       // 0..15 (px group of 4)

    float acc[4][4];
#pragma unroll
    for (int i = 0; i < 4; i++)
#pragma unroll
        for (int j = 0; j < 4; j++) acc[i][j] = 0.f;

    for (int k0 = 0; k0 < C1; k0 += 8) {
        __syncthreads();
        // fill xs: 8 ic x 64 px (float4, coalesced)
        for (int i4 = tid; i4 < 128; i4 += 256) {
            int kc = i4 >> 4, p = (i4 & 15) * 4;
            *(float4*)&xs[kc][p] =
                *(const float4*)&x[(size_t)(b * C1 + k0 + kc) * HW + p0 + p];
        }
        // fill ws: w1[oc][ic], 64 oc x 8 ic
        for (int i = tid; i < 512; i += 256) {
            int oc = i >> 3, kc = i & 7;
            ws[kc][oc] = w1[(oc0 + oc) * C1 + k0 + kc];
        }
        __syncthreads();
#pragma unroll
        for (int kc = 0; kc < 8; kc++) {
            float4 wv = *(float4*)&ws[kc][og * 4];
            float4 xv = *(float4*)&xs[kc][pg * 4];
            float wa[4] = {wv.x, wv.y, wv.z, wv.w};
            float xa[4] = {xv.x, xv.y, xv.z, xv.w};
#pragma unroll
            for (int i = 0; i < 4; i++)
#pragma unroll
                for (int j = 0; j < 4; j++) acc[i][j] += wa[i] * xa[j];
        }
    }

    // epilogue: BN affine + SiLU, store, compute partial sums
    float yv[4][4];
#pragma unroll
    for (int i = 0; i < 4; i++) {
        int oc = oc0 + og * 4 + i;
        float sc = bng[oc] * rsqrtf(bnv[oc] + EPSF);
        float bi = bnb[oc] - bnm[oc] * sc;
#pragma unroll
        for (int j = 0; j < 4; j++) {
            float t = acc[i][j] * sc + bi;
            yv[i][j] = t / (1.f + expf(-t));
        }
        float4 st = {yv[i][0], yv[i][1], yv[i][2], yv[i][3]};
        *(float4*)&g_y[(size_t)(b * C2 + oc) * HW + p0 + pg * 4] = st;
    }
    // deterministic block reduction over the 64 px of this tile
#pragma unroll
    for (int i = 0; i < 4; i++)
        red[og * 4 + i][pg] = yv[i][0] + yv[i][1] + yv[i][2] + yv[i][3];
    __syncthreads();
    if (tid < 64) {
        float t = 0.f;
#pragma unroll
        for (int p = 0; p < 16; p++) t += red[tid][p];
        g_partsum[(size_t)(b * C2 + oc0 + tid) * NPXT + blockIdx.x] = t;
    }
    __syncthreads();
#pragma unroll
    for (int i = 0; i < 4; i++)
        red[og * 4 + i][pg] = yv[i][0] * yv[i][0] + yv[i][1] * yv[i][1] +
                              yv[i][2] * yv[i][2] + yv[i][3] * yv[i][3];
    __syncthreads();
    if (tid < 64) {
        float t = 0.f;
#pragma unroll
        for (int p = 0; p < 16; p++) t += red[tid][p];
        g_partsq[(size_t)(b * C2 + oc0 + tid) * NPXT + blockIdx.x] = t;
    }
}

// ============================================================================
// Kernel B1: reduce partials -> mu, inv_std  (4096 elems)
// ============================================================================
__global__ void k_stats()
{
    int i = blockIdx.x * blockDim.x + threadIdx.x;
    if (i >= BB * C2) return;
    const float* ps = &g_partsum[(size_t)i * NPXT];
    const float* pq = &g_partsq [(size_t)i * NPXT];
    float s = 0.f, q = 0.f;
    for (int j = 0; j < NPXT; j++) { s += ps[j]; q += pq[j]; }
    float mu  = s * (1.f / HW);
    float var = q * (1.f / HW) - mu * mu;
    g_mu[i]  = mu;
    g_inv[i] = rsqrtf(var + EPSF);
}

// ============================================================================
// Kernel B2: attention: pooled(=mu) -> fc1 -> relu -> fc2 -> softmax
// 1 block, 512 threads, warp b handles batch b
// ============================================================================
__global__ void k_attn(
    const float* __restrict__ fc1w, const float* __restrict__ fc1b,
    const float* __restrict__ fc2w, const float* __restrict__ fc2b)
{
    int b = threadIdx.x >> 5;
    int lane = threadIdx.x & 31;
    float p4[KK] = {0.f, 0.f, 0.f, 0.f};
    for (int c = lane; c < C2; c += 32) {
        float pv = g_mu[b * C2 + c];
#pragma unroll
        for (int k = 0; k < KK; k++) p4[k] += pv * fc1w[k * C2 + c];
    }
#pragma unroll
    for (int off = 16; off > 0; off >>= 1)
#pragma unroll
        for (int k = 0; k < KK; k++)
            p4[k] += __shfl_down_sync(0xffffffffu, p4[k], off);
    if (lane == 0) {
        float a[KK];
#pragma unroll
        for (int k = 0; k < KK; k++) a[k] = fmaxf(p4[k] + fc1b[k], 0.f);
        float l[KK];
        float mx = -1e30f;
#pragma unroll
        for (int j = 0; j < KK; j++) {
            float t = fc2b[j];
#pragma unroll
            for (int k = 0; k < KK; k++) t += a[k] * fc2w[j * KK + k];
            l[j] = t;
            mx = fmaxf(mx, t);
        }
        float e[KK], s = 0.f;
#pragma unroll
        for (int j = 0; j < KK; j++) { e[j] = expf(l[j] - mx); s += e[j]; }
        float inv = 1.f / s;
#pragma unroll
        for (int j = 0; j < KK; j++) g_attn[b * KK + j] = e[j] * inv;
    }
}

// ============================================================================
// Kernel C: agg_w[b][ic][tap][oc] = sum_k attn[b,k] * dy_w[k][oc][ic][tap]
//           agg_b[b][oc]          = sum_k attn[b,k] * dy_b[k][oc]
// grid 256, block 256. thread t: oc = t&255, ic = t>>8 -> coalesced writes.
// ============================================================================
__global__ void __launch_bounds__(256) k_agg(
    const float* __restrict__ dyw, const float* __restrict__ dyb)
{
    __shared__ float s_attn[BB * KK];
    if (threadIdx.x < BB * KK) s_attn[threadIdx.x] = g_attn[threadIdx.x];
    __syncthreads();

    int t  = blockIdx.x * 256 + threadIdx.x;
    int oc = t & 255;
    int ic = t >> 8;

    float d[KK][9];
#pragma unroll
    for (int k = 0; k < KK; k++) {
        const float* p = &dyw[((size_t)(k * C2 + oc) * C2 + ic) * 9];
#pragma unroll
        for (int tap = 0; tap < 9; tap++) d[k][tap] = p[tap];
    }
    for (int b = 0; b < BB; b++) {
        float a0 = s_attn[b * KK + 0], a1 = s_attn[b * KK + 1];
        float a2 = s_attn[b * KK + 2], a3 = s_attn[b * KK + 3];
#pragma unroll
        for (int tap = 0; tap < 9; tap++) {
            float w = a0 * d[0][tap] + a1 * d[1][tap] + a2 * d[2][tap] + a3 * d[3][tap];
            g_aggw[((size_t)(b * C2 + ic) * 9 + tap) * C2 + oc] = w;
        }
    }
    if (ic == 0) {
        for (int b = 0; b < BB; b++) {
            float v = 0.f;
#pragma unroll
            for (int k = 0; k < KK; k++)
                v += s_attn[b * KK + k] * dyb[k * C2 + oc];
            g_aggb[b * C2 + oc] = v;
        }
    }
}

// ============================================================================
// Kernel D: per-sample 3x3 conv on instance-normalized y, + agg_b + bn1
// grid (10, 10, 64): z = b*4 + octile. block 256.
// Tile: 64 oc x (8x8) px. Thread = 4oc x 4px (row r, cols c0..c0+3).
// Instance norm fused into smem fill. smem row stride 11 -> conflict-free.
// ============================================================================
__global__ void __launch_bounds__(256) k_dyconv(
    const float* __restrict__ b1g, const float* __restrict__ b1b,
    const float* __restrict__ b1m, const float* __restrict__ b1v,
    float* __restrict__ out)
{
    __shared__ __align__(16) float in_s[8][110];   // [ic][10 rows * stride 11]
    __shared__ __align__(16) float w_s[8][576];    // [ic][tap*64 + oc]

    const int tx  = blockIdx.x, ty = blockIdx.y;
    const int b   = blockIdx.z >> 2;
    const int oc0 = (blockIdx.z & 3) * 64;
    const int tid = threadIdx.x;
    const int og  = tid >> 4;          // 0..15
    const int pg  = tid & 15;          // 0..15
    const int r   = pg >> 1;           // 0..7
    const int c0  = (pg & 1) * 4;      // 0 or 4
    const int muB = b * C2;

    float acc[4][4];
#pragma unroll
    for (int i = 0; i < 4; i++)
#pragma unroll
        for (int j = 0; j < 4; j++) acc[i][j] = 0.f;

    for (int ic0 = 0; ic0 < C2; ic0 += 8) {
        __syncthreads();
        // ---- input halo tile, normalized on the fly ----
        for (int idx = tid; idx < 800; idx += 256) {
            int icc = idx / 100;
            int rem = idx - icc * 100;
            int rr  = rem / 10;
            int cc  = rem - rr * 10;
            int gy  = ty * 8 + rr - 1;
            int gx  = tx * 8 + cc - 1;
            float val = 0.f;
            if ((unsigned)gy < (unsigned)HH && (unsigned)gx < (unsigned)WW) {
                int ch = ic0 + icc;
                float raw = g_y[(size_t)(b * C2 + ch) * HW + gy * WW + gx];
                val = (raw - g_mu[muB + ch]) * g_inv[muB + ch];
            }
            in_s[icc][rr * 11 + cc] = val;
        }
        // ---- weights: [ic][tap][oc64] (float4, coalesced) ----
        for (int i4 = tid; i4 < 1152; i4 += 256) {
            int icc = i4 / 144;
            int rem = i4 - icc * 144;
            int tap = rem >> 4;
            int oc  = (rem & 15) * 4;
            *(float4*)&w_s[icc][tap * 64 + oc] =
                *(const float4*)&g_aggw[((size_t)(b * C2 + ic0 + icc) * 9 + tap) * C2 + oc0 + oc];
        }
        __syncthreads();
        // ---- compute ----
#pragma unroll
        for (int icc = 0; icc < 8; icc++) {
#pragma unroll
            for (int dy = 0; dy < 3; dy++) {
                const float* row = &in_s[icc][(r + dy) * 11 + c0];
                float iv[6];
#pragma unroll
                for (int q = 0; q < 6; q++) iv[q] = row[q];
#pragma unroll
                for (int dx = 0; dx < 3; dx++) {
                    float4 w = *(float4*)&w_s[icc][(dy * 3 + dx) * 64 + og * 4];
                    float wa[4] = {w.x, w.y, w.z, w.w};
#pragma unroll
                    for (int i = 0; i < 4; i++)
#pragma unroll
                        for (int j = 0; j < 4; j++)
                            acc[i][j] += wa[i] * iv[dx + j];
                }
            }
        }
    }

    // ---- epilogue: + agg_b, bn1 affine, store ----
    const int gy  = ty * 8 + r;
    const int gxb = tx * 8 + c0;
#pragma unroll
    for (int i = 0; i < 4; i++) {
        int oc = oc0 + og * 4 + i;
        float sc = b1g[oc] * rsqrtf(b1v[oc] + EPSF);
        float bi = b1b[oc] - b1m[oc] * sc;
        float ab = g_aggb[b * C2 + oc];
        float4 o4;
        o4.x = (acc[i][0] + ab) * sc + bi;
        o4.y = (acc[i][1] + ab) * sc + bi;
        o4.z = (acc[i][2] + ab) * sc + bi;
        o4.w = (acc[i][3] + ab) * sc + bi;
        *(float4*)&out[(size_t)(b * C2 + oc) * HW + gy * WW + gxb] = o4;
    }
}

// ============================================================================
extern "C" void kernel_launch(void* const* d_in, const int* in_sizes, int n_in,
                              void* d_out, int out_size)
{
    (void)in_sizes; (void)n_in; (void)out_size;
    const float* x    = (const float*)d_in[0];
    const float* w1   = (const float*)d_in[1];
    const float* bng  = (const float*)d_in[2];
    const float* bnb  = (const float*)d_in[3];
    const float* bnm  = (const float*)d_in[4];
    const float* bnv  = (const float*)d_in[5];
    const float* fc1w = (const float*)d_in[6];
    const float* fc1b = (const float*)d_in[7];
    const float* fc2w = (const float*)d_in[8];
    const float* fc2b = (const float*)d_in[9];
    const float* dyw  = (const float*)d_in[10];
    const float* dyb  = (const float*)d_in[11];
    const float* b1g  = (const float*)d_in[12];
    const float* b1b  = (const float*)d_in[13];
    const float* b1m  = (const float*)d_in[14];
    const float* b1v  = (const float*)d_in[15];
    float* out = (float*)d_out;

    k_conv1<<<dim3(NPXT, 4, BB), 256>>>(x, w1, bng, bnb, bnm, bnv);
    k_stats<<<(BB * C2 + 255) / 256, 256>>>();
    k_attn<<<1, 512>>>(fc1w, fc1b, fc2w, fc2b);
    k_agg<<<256, 256>>>(dyw, dyb);
    k_dyconv<<<dim3(10, 10, BB * 4), 256>>>(b1g, b1b, b1m, b1v, out);
}

// round 2
// speedup vs baseline: 1.0429x; 1.0429x over previous
#include <cuda_runtime.h>
#include <math.h>

#define BB 16
#define C1 128
#define C2 256
#define KK 4
#define HH 80
#define WW 80
#define HW 6400
#define EPSF 1e-5f
#define NPXT 100   // 6400/64 px tiles in kernel A

// ---------------- packed fp32x2 helpers (Blackwell FFMA2 path) ----------------
__device__ __forceinline__ void ffma2(unsigned long long& d,
                                      unsigned long long a,
                                      unsigned long long b) {
    asm("fma.rn.f32x2 %0, %1, %2, %0;" : "+l"(d) : "l"(a), "l"(b));
}
__device__ __forceinline__ unsigned long long pack2(float lo, float hi) {
    unsigned long long r;
    asm("mov.b64 %0, {%1, %2};" : "=l"(r) : "f"(lo), "f"(hi));
    return r;
}
__device__ __forceinline__ void unpack2(float& lo, float& hi, unsigned long long v) {
    asm("mov.b64 {%0, %1}, %2;" : "=f"(lo), "=f"(hi) : "l"(v));
}

// ---------------- scratch (static device globals; no allocs) ----------------
__device__ float g_y[BB * C2 * HW];            // post conv1+BN+SiLU feature
__device__ float g_partsum[BB * C2 * NPXT];    // per-(b,c) partial sums (deterministic)
__device__ float g_partsq [BB * C2 * NPXT];
__device__ float g_mu [BB * C2];
__device__ float g_inv[BB * C2];
__device__ float g_attn[BB * KK];
__device__ float g_aggw[BB * C2 * 9 * C2];     // [b][ic][tap][oc]
__device__ float g_aggb[BB * C2];

// ============================================================================
// Kernel A: y = SiLU(BN(x @ W1))  + per-(b,c) partial sum / sumsq over px tile
// grid (100, 4, 16), block 256.  Tile: 64 px x 64 oc, thread = 4oc x 4px.
// Inner product uses fma.rn.f32x2 (px-paired).
// ============================================================================
__global__ void __launch_bounds__(256) k_conv1(
    const float* __restrict__ x, const float* __restrict__ w1,
    const float* __restrict__ bng, const float* __restrict__ bnb,
    const float* __restrict__ bnm, const float* __restrict__ bnv)
{
    __shared__ __align__(16) float xs[8][64];
    __shared__ __align__(16) float ws[8][64];
    __shared__ float red[64][17];

    const int b   = blockIdx.z;
    const int oc0 = blockIdx.y * 64;
    const int p0  = blockIdx.x * 64;
    const int tid = threadIdx.x;
    const int og  = tid >> 4;       // 0..15 (oc group of 4)
    const int pg  = tid & 15;       // 0..15 (px group of 4)

    unsigned long long acc2[4][2];  // [oc i][px pair]
#pragma unroll
    for (int i = 0; i < 4; i++) { acc2[i][0] = 0ull; acc2[i][1] = 0ull; }

    for (int k0 = 0; k0 < C1; k0 += 8) {
        __syncthreads();
        // fill xs: 8 ic x 64 px (float4, coalesced)
        for (int i4 = tid; i4 < 128; i4 += 256) {
            int kc = i4 >> 4, p = (i4 & 15) * 4;
            *(float4*)&xs[kc][p] =
                *(const float4*)&x[(size_t)(b * C1 + k0 + kc) * HW + p0 + p];
        }
        // fill ws: w1[oc][ic], 64 oc x 8 ic
        for (int i = tid; i < 512; i += 256) {
            int oc = i >> 3, kc = i & 7;
            ws[kc][oc] = w1[(oc0 + oc) * C1 + k0 + kc];
        }
        __syncthreads();
#pragma unroll
        for (int kc = 0; kc < 8; kc++) {
            ulonglong2 xv = *(const ulonglong2*)&xs[kc][pg * 4]; // (px0,px1),(px2,px3)
            float4 wv = *(const float4*)&ws[kc][og * 4];
            unsigned long long wb[4];
            wb[0] = pack2(wv.x, wv.x);
            wb[1] = pack2(wv.y, wv.y);
            wb[2] = pack2(wv.z, wv.z);
            wb[3] = pack2(wv.w, wv.w);
#pragma unroll
            for (int i = 0; i < 4; i++) {
                ffma2(acc2[i][0], wb[i], xv.x);
                ffma2(acc2[i][1], wb[i], xv.y);
            }
        }
    }

    // epilogue: BN affine + SiLU, store, compute partial sums
    float yv[4][4];
#pragma unroll
    for (int i = 0; i < 4; i++) {
        float a0, a1, a2, a3;
        unpack2(a0, a1, acc2[i][0]);
        unpack2(a2, a3, acc2[i][1]);
        float av[4] = {a0, a1, a2, a3};
        int oc = oc0 + og * 4 + i;
        float sc = bng[oc] * rsqrtf(bnv[oc] + EPSF);
        float bi = bnb[oc] - bnm[oc] * sc;
#pragma unroll
        for (int j = 0; j < 4; j++) {
            float t = av[j] * sc + bi;
            yv[i][j] = t / (1.f + expf(-t));
        }
        float4 st = {yv[i][0], yv[i][1], yv[i][2], yv[i][3]};
        *(float4*)&g_y[(size_t)(b * C2 + oc) * HW + p0 + pg * 4] = st;
    }
    // deterministic block reduction over the 64 px of this tile
#pragma unroll
    for (int i = 0; i < 4; i++)
        red[og * 4 + i][pg] = yv[i][0] + yv[i][1] + yv[i][2] + yv[i][3];
    __syncthreads();
    if (tid < 64) {
        float t = 0.f;
#pragma unroll
        for (int p = 0; p < 16; p++) t += red[tid][p];
        g_partsum[(size_t)(b * C2 + oc0 + tid) * NPXT + blockIdx.x] = t;
    }
    __syncthreads();
#pragma unroll
    for (int i = 0; i < 4; i++)
        red[og * 4 + i][pg] = yv[i][0] * yv[i][0] + yv[i][1] * yv[i][1] +
                              yv[i][2] * yv[i][2] + yv[i][3] * yv[i][3];
    __syncthreads();
    if (tid < 64) {
        float t = 0.f;
#pragma unroll
        for (int p = 0; p < 16; p++) t += red[tid][p];
        g_partsq[(size_t)(b * C2 + oc0 + tid) * NPXT + blockIdx.x] = t;
    }
}

// ============================================================================
// Kernel B1: reduce partials -> mu, inv_std  (4096 elems)
// ============================================================================
__global__ void k_stats()
{
    int i = blockIdx.x * blockDim.x + threadIdx.x;
    if (i >= BB * C2) return;
    const float* ps = &g_partsum[(size_t)i * NPXT];
    const float* pq = &g_partsq [(size_t)i * NPXT];
    float s = 0.f, q = 0.f;
    for (int j = 0; j < NPXT; j++) { s += ps[j]; q += pq[j]; }
    float mu  = s * (1.f / HW);
    float var = q * (1.f / HW) - mu * mu;
    g_mu[i]  = mu;
    g_inv[i] = rsqrtf(var + EPSF);
}

// ============================================================================
// Kernel B2: attention: pooled(=mu) -> fc1 -> relu -> fc2 -> softmax
// ============================================================================
__global__ void k_attn(
    const float* __restrict__ fc1w, const float* __restrict__ fc1b,
    const float* __restrict__ fc2w, const float* __restrict__ fc2b)
{
    int b = threadIdx.x >> 5;
    int lane = threadIdx.x & 31;
    float p4[KK] = {0.f, 0.f, 0.f, 0.f};
    for (int c = lane; c < C2; c += 32) {
        float pv = g_mu[b * C2 + c];
#pragma unroll
        for (int k = 0; k < KK; k++) p4[k] += pv * fc1w[k * C2 + c];
    }
#pragma unroll
    for (int off = 16; off > 0; off >>= 1)
#pragma unroll
        for (int k = 0; k < KK; k++)
            p4[k] += __shfl_down_sync(0xffffffffu, p4[k], off);
    if (lane == 0) {
        float a[KK];
#pragma unroll
        for (int k = 0; k < KK; k++) a[k] = fmaxf(p4[k] + fc1b[k], 0.f);
        float l[KK];
        float mx = -1e30f;
#pragma unroll
        for (int j = 0; j < KK; j++) {
            float t = fc2b[j];
#pragma unroll
            for (int k = 0; k < KK; k++) t += a[k] * fc2w[j * KK + k];
            l[j] = t;
            mx = fmaxf(mx, t);
        }
        float e[KK], s = 0.f;
#pragma unroll
        for (int j = 0; j < KK; j++) { e[j] = expf(l[j] - mx); s += e[j]; }
        float inv = 1.f / s;
#pragma unroll
        for (int j = 0; j < KK; j++) g_attn[b * KK + j] = e[j] * inv;
    }
}

// ============================================================================
// Kernel C: agg_w[b][ic][tap][oc] = sum_k attn[b,k] * dy_w[k][oc][ic][tap]
// ============================================================================
__global__ void __launch_bounds__(256) k_agg(
    const float* __restrict__ dyw, const float* __restrict__ dyb)
{
    __shared__ float s_attn[BB * KK];
    if (threadIdx.x < BB * KK) s_attn[threadIdx.x] = g_attn[threadIdx.x];
    __syncthreads();

    int t  = blockIdx.x * 256 + threadIdx.x;
    int oc = t & 255;
    int ic = t >> 8;

    float d[KK][9];
#pragma unroll
    for (int k = 0; k < KK; k++) {
        const float* p = &dyw[((size_t)(k * C2 + oc) * C2 + ic) * 9];
#pragma unroll
        for (int tap = 0; tap < 9; tap++) d[k][tap] = p[tap];
    }
    for (int b = 0; b < BB; b++) {
        float a0 = s_attn[b * KK + 0], a1 = s_attn[b * KK + 1];
        float a2 = s_attn[b * KK + 2], a3 = s_attn[b * KK + 3];
#pragma unroll
        for (int tap = 0; tap < 9; tap++) {
            float w = a0 * d[0][tap] + a1 * d[1][tap] + a2 * d[2][tap] + a3 * d[3][tap];
            g_aggw[((size_t)(b * C2 + ic) * 9 + tap) * C2 + oc] = w;
        }
    }
    if (ic == 0) {
        for (int b = 0; b < BB; b++) {
            float v = 0.f;
#pragma unroll
            for (int k = 0; k < KK; k++)
                v += s_attn[b * KK + k] * dyb[k * C2 + oc];
            g_aggb[b * C2 + oc] = v;
        }
    }
}

// ============================================================================
// Kernel D: per-sample 3x3 conv on instance-normalized y, + agg_b + bn1
// grid (10, 10, 64): z = b*4 + octile. block 256.
// Tile: 64 oc x (8x8) px. Thread = 4oc x 4px. Compute uses fma.rn.f32x2
// paired over oc: weight pairs come free from 16B smem loads; input broadcast
// pairs packed once per (ic, ky) and reused across 3 kx x 4 px.
// ============================================================================
__global__ void __launch_bounds__(256) k_dyconv(
    const float* __restrict__ b1g, const float* __restrict__ b1b,
    const float* __restrict__ b1m, const float* __restrict__ b1v,
    float* __restrict__ out)
{
    __shared__ __align__(16) float in_s[8][110];   // [ic][10 rows * stride 11]
    __shared__ __align__(16) float w_s[8][576];    // [ic][tap*64 + oc]
    __shared__ float s_mu[C2], s_inv[C2];

    const int tx  = blockIdx.x, ty = blockIdx.y;
    const int b   = blockIdx.z >> 2;
    const int oc0 = (blockIdx.z & 3) * 64;
    const int tid = threadIdx.x;
    const int og  = tid >> 4;          // 0..15
    const int pg  = tid & 15;          // 0..15
    const int r   = pg >> 1;           // 0..7
    const int c0  = (pg & 1) * 4;      // 0 or 4

    // preload per-channel IN stats (256 threads, C2 = 256)
    s_mu[tid]  = g_mu[b * C2 + tid];
    s_inv[tid] = g_inv[b * C2 + tid];

    unsigned long long acc2[2][4];     // [oc pair][px j]
#pragma unroll
    for (int i = 0; i < 2; i++)
#pragma unroll
        for (int j = 0; j < 4; j++) acc2[i][j] = 0ull;

    for (int ic0 = 0; ic0 < C2; ic0 += 8) {
        __syncthreads();
        // ---- input halo tile, normalized on the fly ----
        for (int idx = tid; idx < 800; idx += 256) {
            int icc = idx / 100;
            int rem = idx - icc * 100;
            int rr  = rem / 10;
            int cc  = rem - rr * 10;
            int gy  = ty * 8 + rr - 1;
            int gx  = tx * 8 + cc - 1;
            float val = 0.f;
            if ((unsigned)gy < (unsigned)HH && (unsigned)gx < (unsigned)WW) {
                int ch = ic0 + icc;
                float raw = g_y[(size_t)(b * C2 + ch) * HW + gy * WW + gx];
                val = (raw - s_mu[ch]) * s_inv[ch];
            }
            in_s[icc][rr * 11 + cc] = val;
        }
        // ---- weights: [ic][tap][oc64] (float4, coalesced) ----
        for (int i4 = tid; i4 < 1152; i4 += 256) {
            int icc = i4 / 144;
            int rem = i4 - icc * 144;
            int tap = rem >> 4;
            int oc  = (rem & 15) * 4;
            *(float4*)&w_s[icc][tap * 64 + oc] =
                *(const float4*)&g_aggw[((size_t)(b * C2 + ic0 + icc) * 9 + tap) * C2 + oc0 + oc];
        }
        __syncthreads();
        // ---- compute (FFMA2) ----
#pragma unroll
        for (int icc = 0; icc < 8; icc++) {
#pragma unroll
            for (int dy = 0; dy < 3; dy++) {
                const float* row = &in_s[icc][(r + dy) * 11 + c0];
                unsigned long long ivb[6];
#pragma unroll
                for (int q = 0; q < 6; q++) {
                    float v = row[q];
                    ivb[q] = pack2(v, v);
                }
#pragma unroll
                for (int dx = 0; dx < 3; dx++) {
                    ulonglong2 w2 = *(const ulonglong2*)&w_s[icc][(dy * 3 + dx) * 64 + og * 4];
#pragma unroll
                    for (int j = 0; j < 4; j++) {
                        ffma2(acc2[0][j], w2.x, ivb[dx + j]);
                        ffma2(acc2[1][j], w2.y, ivb[dx + j]);
                    }
                }
            }
        }
    }

    // ---- unpack accumulators: accs[i][j], i = oc-in-group, j = px ----
    float accs[4][4];
#pragma unroll
    for (int j = 0; j < 4; j++) {
        unpack2(accs[0][j], accs[1][j], acc2[0][j]);
        unpack2(accs[2][j], accs[3][j], acc2[1][j]);
    }

    // ---- epilogue: + agg_b, bn1 affine, store ----
    const int gy  = ty * 8 + r;
    const int gxb = tx * 8 + c0;
#pragma unroll
    for (int i = 0; i < 4; i++) {
        int oc = oc0 + og * 4 + i;
        float sc = b1g[oc] * rsqrtf(b1v[oc] + EPSF);
        float bi = b1b[oc] - b1m[oc] * sc;
        float ab = g_aggb[b * C2 + oc];
        float4 o4;
        o4.x = (accs[i][0] + ab) * sc + bi;
        o4.y = (accs[i][1] + ab) * sc + bi;
        o4.z = (accs[i][2] + ab) * sc + bi;
        o4.w = (accs[i][3] + ab) * sc + bi;
        *(float4*)&out[(size_t)(b * C2 + oc) * HW + gy * WW + gxb] = o4;
    }
}

// ============================================================================
extern "C" void kernel_launch(void* const* d_in, const int* in_sizes, int n_in,
                              void* d_out, int out_size)
{
    (void)in_sizes; (void)n_in; (void)out_size;
    const float* x    = (const float*)d_in[0];
    const float* w1   = (const float*)d_in[1];
    const float* bng  = (const float*)d_in[2];
    const float* bnb  = (const float*)d_in[3];
    const float* bnm  = (const float*)d_in[4];
    const float* bnv  = (const float*)d_in[5];
    const float* fc1w = (const float*)d_in[6];
    const float* fc1b = (const float*)d_in[7];
    const float* fc2w = (const float*)d_in[8];
    const float* fc2b = (const float*)d_in[9];
    const float* dyw  = (const float*)d_in[10];
    const float* dyb  = (const float*)d_in[11];
    const float* b1g  = (const float*)d_in[12];
    const float* b1b  = (const float*)d_in[13];
    const float* b1m  = (const float*)d_in[14];
    const float* b1v  = (const float*)d_in[15];
    float* out = (float*)d_out;

    k_conv1<<<dim3(NPXT, 4, BB), 256>>>(x, w1, bng, bnb, bnm, bnv);
    k_stats<<<(BB * C2 + 255) / 256, 256>>>();
    k_attn<<<1, 512>>>(fc1w, fc1b, fc2w, fc2b);
    k_agg<<<256, 256>>>(dyw, dyb);
    k_dyconv<<<dim3(10, 10, BB * 4), 256>>>(b1g, b1b, b1m, b1v, out);
}

// round 4
// speedup vs baseline: 1.9373x; 1.8576x over previous
#include <cuda_runtime.h>
#include <math.h>
#include <stdint.h>

#define BB 16
#define C1 128
#define C2 256
#define KK 4
#define HH 80
#define WW 80
#define HW 6400
#define EPSF 1e-5f
#define NPXT 100   // 6400/64 px tiles in kernel A

// ---------------- packed fp32x2 helpers (kept for k_conv1) ----------------
__device__ __forceinline__ void ffma2(unsigned long long& d,
                                      unsigned long long a,
                                      unsigned long long b) {
    asm("fma.rn.f32x2 %0, %1, %2, %0;" : "+l"(d) : "l"(a), "l"(b));
}
__device__ __forceinline__ unsigned long long pack2(float lo, float hi) {
    unsigned long long r;
    asm("mov.b64 %0, {%1, %2};" : "=l"(r) : "f"(lo), "f"(hi));
    return r;
}
__device__ __forceinline__ void unpack2(float& lo, float& hi, unsigned long long v) {
    asm("mov.b64 {%0, %1}, %2;" : "=f"(lo), "=f"(hi) : "l"(v));
}
// tf32 round-to-nearest
__device__ __forceinline__ uint32_t tf32r(float f) {
    uint32_t r;
    asm("cvt.rna.tf32.f32 %0, %1;" : "=r"(r) : "f"(f));
    return r;
}

// ---------------- scratch (static device globals; no allocs) ----------------
__device__ float g_y[BB * C2 * HW];            // post conv1+BN+SiLU feature
__device__ float g_partsum[BB * C2 * NPXT];
__device__ float g_partsq [BB * C2 * NPXT];
__device__ float g_mu [BB * C2];
__device__ float g_inv[BB * C2];
__device__ float g_attn[BB * KK];
__device__ float g_aggw[BB * C2 * 9 * C2];     // [b][ic][tap][oc], tf32-rounded values
__device__ float g_aggb[BB * C2];

// ============================================================================
// Kernel A: y = SiLU(BN(x @ W1)) + per-(b,c) partial sum / sumsq
// ============================================================================
__global__ void __launch_bounds__(256) k_conv1(
    const float* __restrict__ x, const float* __restrict__ w1,
    const float* __restrict__ bng, const float* __restrict__ bnb,
    const float* __restrict__ bnm, const float* __restrict__ bnv)
{
    __shared__ __align__(16) float xs[8][64];
    __shared__ __align__(16) float ws[8][64];
    __shared__ float red[64][17];

    const int b   = blockIdx.z;
    const int oc0 = blockIdx.y * 64;
    const int p0  = blockIdx.x * 64;
    const int tid = threadIdx.x;
    const int og  = tid >> 4;
    const int pg  = tid & 15;

    unsigned long long acc2[4][2];
#pragma unroll
    for (int i = 0; i < 4; i++) { acc2[i][0] = 0ull; acc2[i][1] = 0ull; }

    for (int k0 = 0; k0 < C1; k0 += 8) {
        __syncthreads();
        for (int i4 = tid; i4 < 128; i4 += 256) {
            int kc = i4 >> 4, p = (i4 & 15) * 4;
            *(float4*)&xs[kc][p] =
                *(const float4*)&x[(size_t)(b * C1 + k0 + kc) * HW + p0 + p];
        }
        for (int i = tid; i < 512; i += 256) {
            int oc = i >> 3, kc = i & 7;
            ws[kc][oc] = w1[(oc0 + oc) * C1 + k0 + kc];
        }
        __syncthreads();
#pragma unroll
        for (int kc = 0; kc < 8; kc++) {
            ulonglong2 xv = *(const ulonglong2*)&xs[kc][pg * 4];
            float4 wv = *(const float4*)&ws[kc][og * 4];
            unsigned long long wb[4];
            wb[0] = pack2(wv.x, wv.x);
            wb[1] = pack2(wv.y, wv.y);
            wb[2] = pack2(wv.z, wv.z);
            wb[3] = pack2(wv.w, wv.w);
#pragma unroll
            for (int i = 0; i < 4; i++) {
                ffma2(acc2[i][0], wb[i], xv.x);
                ffma2(acc2[i][1], wb[i], xv.y);
            }
        }
    }

    float yv[4][4];
#pragma unroll
    for (int i = 0; i < 4; i++) {
        float a0, a1, a2, a3;
        unpack2(a0, a1, acc2[i][0]);
        unpack2(a2, a3, acc2[i][1]);
        float av[4] = {a0, a1, a2, a3};
        int oc = oc0 + og * 4 + i;
        float sc = bng[oc] * rsqrtf(bnv[oc] + EPSF);
        float bi = bnb[oc] - bnm[oc] * sc;
#pragma unroll
        for (int j = 0; j < 4; j++) {
            float t = av[j] * sc + bi;
            yv[i][j] = t / (1.f + expf(-t));
        }
        float4 st = {yv[i][0], yv[i][1], yv[i][2], yv[i][3]};
        *(float4*)&g_y[(size_t)(b * C2 + oc) * HW + p0 + pg * 4] = st;
    }
#pragma unroll
    for (int i = 0; i < 4; i++)
        red[og * 4 + i][pg] = yv[i][0] + yv[i][1] + yv[i][2] + yv[i][3];
    __syncthreads();
    if (tid < 64) {
        float t = 0.f;
#pragma unroll
        for (int p = 0; p < 16; p++) t += red[tid][p];
        g_partsum[(size_t)(b * C2 + oc0 + tid) * NPXT + blockIdx.x] = t;
    }
    __syncthreads();
#pragma unroll
    for (int i = 0; i < 4; i++)
        red[og * 4 + i][pg] = yv[i][0] * yv[i][0] + yv[i][1] * yv[i][1] +
                              yv[i][2] * yv[i][2] + yv[i][3] * yv[i][3];
    __syncthreads();
    if (tid < 64) {
        float t = 0.f;
#pragma unroll
        for (int p = 0; p < 16; p++) t += red[tid][p];
        g_partsq[(size_t)(b * C2 + oc0 + tid) * NPXT + blockIdx.x] = t;
    }
}

// ============================================================================
// Kernel B1: reduce partials -> mu, inv_std
// ============================================================================
__global__ void k_stats()
{
    int i = blockIdx.x * blockDim.x + threadIdx.x;
    if (i >= BB * C2) return;
    const float* ps = &g_partsum[(size_t)i * NPXT];
    const float* pq = &g_partsq [(size_t)i * NPXT];
    float s = 0.f, q = 0.f;
    for (int j = 0; j < NPXT; j++) { s += ps[j]; q += pq[j]; }
    float mu  = s * (1.f / HW);
    float var = q * (1.f / HW) - mu * mu;
    g_mu[i]  = mu;
    g_inv[i] = rsqrtf(var + EPSF);
}

// ============================================================================
// Kernel B2: attention
// ============================================================================
__global__ void k_attn(
    const float* __restrict__ fc1w, const float* __restrict__ fc1b,
    const float* __restrict__ fc2w, const float* __restrict__ fc2b)
{
    int b = threadIdx.x >> 5;
    int lane = threadIdx.x & 31;
    float p4[KK] = {0.f, 0.f, 0.f, 0.f};
    for (int c = lane; c < C2; c += 32) {
        float pv = g_mu[b * C2 + c];
#pragma unroll
        for (int k = 0; k < KK; k++) p4[k] += pv * fc1w[k * C2 + c];
    }
#pragma unroll
    for (int off = 16; off > 0; off >>= 1)
#pragma unroll
        for (int k = 0; k < KK; k++)
            p4[k] += __shfl_down_sync(0xffffffffu, p4[k], off);
    if (lane == 0) {
        float a[KK];
#pragma unroll
        for (int k = 0; k < KK; k++) a[k] = fmaxf(p4[k] + fc1b[k], 0.f);
        float l[KK];
        float mx = -1e30f;
#pragma unroll
        for (int j = 0; j < KK; j++) {
            float t = fc2b[j];
#pragma unroll
            for (int k = 0; k < KK; k++) t += a[k] * fc2w[j * KK + k];
            l[j] = t;
            mx = fmaxf(mx, t);
        }
        float e[KK], s = 0.f;
#pragma unroll
        for (int j = 0; j < KK; j++) { e[j] = expf(l[j] - mx); s += e[j]; }
        float inv = 1.f / s;
#pragma unroll
        for (int j = 0; j < KK; j++) g_attn[b * KK + j] = e[j] * inv;
    }
}

// ============================================================================
// Kernel C: agg_w[b][ic][tap][oc] (tf32-rounded), agg_b[b][oc]
// ============================================================================
__global__ void __launch_bounds__(256) k_agg(
    const float* __restrict__ dyw, const float* __restrict__ dyb)
{
    __shared__ float s_attn[BB * KK];
    if (threadIdx.x < BB * KK) s_attn[threadIdx.x] = g_attn[threadIdx.x];
    __syncthreads();

    int t  = blockIdx.x * 256 + threadIdx.x;
    int oc = t & 255;
    int ic = t >> 8;

    float d[KK][9];
#pragma unroll
    for (int k = 0; k < KK; k++) {
        const float* p = &dyw[((size_t)(k * C2 + oc) * C2 + ic) * 9];
#pragma unroll
        for (int tap = 0; tap < 9; tap++) d[k][tap] = p[tap];
    }
    for (int b = 0; b < BB; b++) {
        float a0 = s_attn[b * KK + 0], a1 = s_attn[b * KK + 1];
        float a2 = s_attn[b * KK + 2], a3 = s_attn[b * KK + 3];
#pragma unroll
        for (int tap = 0; tap < 9; tap++) {
            float w = a0 * d[0][tap] + a1 * d[1][tap] + a2 * d[2][tap] + a3 * d[3][tap];
            g_aggw[((size_t)(b * C2 + ic) * 9 + tap) * C2 + oc] =
                __uint_as_float(tf32r(w));   // pre-round to tf32
        }
    }
    if (ic == 0) {
        for (int b = 0; b < BB; b++) {
            float v = 0.f;
#pragma unroll
            for (int k = 0; k < KK; k++)
                v += s_attn[b * KK + k] * dyb[k * C2 + oc];
            g_aggb[b * C2 + oc] = v;
        }
    }
}

// ============================================================================
// Kernel D: per-sample 3x3 conv as implicit TF32 GEMM (mma.sync m16n8k8)
//
// Per block: C[128 oc, 128 px] += A[k, oc] * B[k, px], K = 9 taps * 256 ic.
// Stage = one tap x 32 ic. px tile = 8 rows x 16 cols.
// grid (50, 2, 16), block 256 = 8 warps (4 M x 2 N), warp tile 32oc x 64px.
// B fill = shifted copy of g_y with instance-norm fused; OOB -> 0.
// Register-prefetch double buffering (LDG next stage under MMA of current).
// ============================================================================
#define AST 136   // smem k-row stride (136 % 32 == 8 -> conflict-free frags)

__global__ void __launch_bounds__(256) k_dyconv(
    const float* __restrict__ b1g, const float* __restrict__ b1b,
    const float* __restrict__ b1m, const float* __restrict__ b1v,
    float* __restrict__ out)
{
    __shared__ uint32_t As[32][AST];   // [k][oc]  (tf32 bits)
    __shared__ uint32_t Bs[32][AST];   // [k][px]  (tf32 bits)
    __shared__ float s_mu[C2], s_inv[C2];

    const int tid = threadIdx.x;
    const int b   = blockIdx.z;
    const int oc0 = blockIdx.y * 128;
    const int tyx = blockIdx.x;          // 0..49
    const int gy0 = (tyx / 5) * 8;
    const int gx0 = (tyx % 5) * 16;

    const int warp = tid >> 5;
    const int lane = tid & 31;
    const int wm   = warp >> 1;          // 0..3
    const int wn   = warp & 1;           // 0..1
    const int lr   = lane >> 2;          // 0..7
    const int lc   = lane & 3;           // 0..3

    // stage-fill thread mapping
    const int a_row  = tid >> 3;         // 0..31  (k)
    const int a_col  = (tid & 7) * 16;   // 0..112 (oc)
    const int b_n0   = (tid & 31) * 4;   // 0..124 (px)
    const int b_kb   = tid >> 5;         // 0..7   (k base)

    s_mu[tid]  = g_mu[b * C2 + tid];
    s_inv[tid] = g_inv[b * C2 + tid];
    __syncthreads();

    float acc[2][8][4];
#pragma unroll
    for (int mt = 0; mt < 2; mt++)
#pragma unroll
        for (int nt = 0; nt < 8; nt++)
#pragma unroll
            for (int q = 0; q < 4; q++) acc[mt][nt][q] = 0.f;

    float4 avr[4];
    float  bvr[4][4];

    // ---- load stage s into registers ----
    auto load_stage = [&](int s) {
        const int tap = s >> 3;
        const int ic0 = (s & 7) * 32;
        const int dy  = tap / 3 - 1;
        const int dx  = tap % 3 - 1;
        // A: 4 x float4
        const float* ap = &g_aggw[((size_t)(b * C2 + ic0 + a_row) * 9 + tap) * C2 + oc0 + a_col];
#pragma unroll
        for (int t = 0; t < 4; t++) avr[t] = *(const float4*)(ap + t * 4);
        // B: 4 k-rows x 4 px
        const int sr  = b_n0 >> 4;          // spatial row in tile
        const int scb = b_n0 & 15;          // spatial col base
        const int gy  = gy0 + sr + dy;
        const int gxb = gx0 + scb + dx;
        const bool yok = (unsigned)gy < (unsigned)HH;
#pragma unroll
        for (int kk = 0; kk < 4; kk++) {
            const int ic = ic0 + b_kb + kk * 8;
            const float mu  = s_mu[ic];
            const float inv = s_inv[ic];
            const float* src = &g_y[(size_t)(b * C2 + ic) * HW + gy * WW + gxb];
#pragma unroll
            for (int q = 0; q < 4; q++) {
                const int gx = gxb + q;
                float v = 0.f;
                if (yok && (unsigned)gx < (unsigned)WW)
                    v = (src[q] - mu) * inv;
                bvr[kk][q] = v;
            }
        }
    };

    // ---- store registers into smem (with tf32 round for B) ----
    auto store_stage = [&]() {
#pragma unroll
        for (int t = 0; t < 4; t++)
            *(float4*)&As[a_row][a_col + t * 4] = avr[t];
#pragma unroll
        for (int kk = 0; kk < 4; kk++)
#pragma unroll
            for (int q = 0; q < 4; q++)
                Bs[b_kb + kk * 8][b_n0 + q] = tf32r(bvr[kk][q]);
    };

    load_stage(0);

    for (int s = 0; s < 72; s++) {
        __syncthreads();
        store_stage();
        __syncthreads();
        if (s < 71) load_stage(s + 1);

        // ---- compute: 4 k-steps x (2 m-tiles x 8 n-tiles) mma ----
#pragma unroll
        for (int ks = 0; ks < 4; ks++) {
            const int k0 = ks * 8;
            uint32_t afr[2][4];
#pragma unroll
            for (int mt = 0; mt < 2; mt++) {
                const int oc = wm * 32 + mt * 16 + lr;
                afr[mt][0] = As[k0 + lc][oc];
                afr[mt][1] = As[k0 + lc][oc + 8];
                afr[mt][2] = As[k0 + lc + 4][oc];
                afr[mt][3] = As[k0 + lc + 4][oc + 8];
            }
            uint32_t bfr[8][2];
#pragma unroll
            for (int nt = 0; nt < 8; nt++) {
                const int n = wn * 64 + nt * 8 + lr;
                bfr[nt][0] = Bs[k0 + lc][n];
                bfr[nt][1] = Bs[k0 + lc + 4][n];
            }
#pragma unroll
            for (int mt = 0; mt < 2; mt++)
#pragma unroll
                for (int nt = 0; nt < 8; nt++)
                    asm volatile(
                        "mma.sync.aligned.m16n8k8.row.col.f32.tf32.tf32.f32 "
                        "{%0,%1,%2,%3}, {%4,%5,%6,%7}, {%8,%9}, {%0,%1,%2,%3};"
                        : "+f"(acc[mt][nt][0]), "+f"(acc[mt][nt][1]),
                          "+f"(acc[mt][nt][2]), "+f"(acc[mt][nt][3])
                        : "r"(afr[mt][0]), "r"(afr[mt][1]),
                          "r"(afr[mt][2]), "r"(afr[mt][3]),
                          "r"(bfr[nt][0]), "r"(bfr[nt][1]));
        }
    }

    // ---- epilogue: + agg_b, bn1 affine, store (float2 per c-pair) ----
#pragma unroll
    for (int mt = 0; mt < 2; mt++) {
#pragma unroll
        for (int h = 0; h < 2; h++) {
            const int oc = oc0 + wm * 32 + mt * 16 + lr + h * 8;
            const float sc = b1g[oc] * rsqrtf(b1v[oc] + EPSF);
            const float bi = b1b[oc] - b1m[oc] * sc;
            const float ab = g_aggb[b * C2 + oc];
            float* obase = &out[(size_t)(b * C2 + oc) * HW];
#pragma unroll
            for (int nt = 0; nt < 8; nt++) {
                const int n0 = wn * 64 + nt * 8 + 2 * lc;
                const int gy = gy0 + (n0 >> 4);
                const int gx = gx0 + (n0 & 15);
                float2 o;
                o.x = (acc[mt][nt][h * 2 + 0] + ab) * sc + bi;
                o.y = (acc[mt][nt][h * 2 + 1] + ab) * sc + bi;
                *(float2*)&obase[gy * WW + gx] = o;
            }
        }
    }
}

// ============================================================================
extern "C" void kernel_launch(void* const* d_in, const int* in_sizes, int n_in,
                              void* d_out, int out_size)
{
    (void)in_sizes; (void)n_in; (void)out_size;
    const float* x    = (const float*)d_in[0];
    const float* w1   = (const float*)d_in[1];
    const float* bng  = (const float*)d_in[2];
    const float* bnb  = (const float*)d_in[3];
    const float* bnm  = (const float*)d_in[4];
    const float* bnv  = (const float*)d_in[5];
    const float* fc1w = (const float*)d_in[6];
    const float* fc1b = (const float*)d_in[7];
    const float* fc2w = (const float*)d_in[8];
    const float* fc2b = (const float*)d_in[9];
    const float* dyw  = (const float*)d_in[10];
    const float* dyb  = (const float*)d_in[11];
    const float* b1g  = (const float*)d_in[12];
    const float* b1b  = (const float*)d_in[13];
    const float* b1m  = (const float*)d_in[14];
    const float* b1v  = (const float*)d_in[15];
    float* out = (float*)d_out;

    k_conv1<<<dim3(NPXT, 4, BB), 256>>>(x, w1, bng, bnb, bnm, bnv);
    k_stats<<<(BB * C2 + 255) / 256, 256>>>();
    k_attn<<<1, 512>>>(fc1w, fc1b, fc2w, fc2b);
    k_agg<<<256, 256>>>(dyw, dyb);
    k_dyconv<<<dim3(50, 2, BB), 256>>>(b1g, b1b, b1m, b1v, out);
}